// round 1
// baseline (speedup 1.0000x reference)
#include <cuda_runtime.h>
#include <cuda_bf16.h>
#include <stdint.h>

// Problem constants
#define M_PTS 16384   // B*N = 8*2048
#define D_DIM 256
#define C_CODES 8192

// GEMM tiling
#define TM 128
#define TC 128
#define TK 16

// Scratch (no cudaMalloc allowed)
__device__ unsigned long long g_best[M_PTS];
__device__ float g_x2[M_PTS];
__device__ float g_e2[C_CODES];

// ---------------------------------------------------------------------------
// init best keys
__global__ void init_best_kernel(unsigned long long* best, int n) {
    int i = blockIdx.x * blockDim.x + threadIdx.x;
    if (i < n) best[i] = 0xFFFFFFFFFFFFFFFFull;
}

// ---------------------------------------------------------------------------
// row sum of squares: one warp per row of length 256.
// Mimics elementwise square (rounded) then reduce: strided per-lane sequential
// accumulation + shfl-down tree (XLA-GPU-style row reduction).
__global__ void rowsumsq_kernel(const float* __restrict__ a,
                                float* __restrict__ out, int rows) {
    int row = blockIdx.x * (blockDim.x >> 5) + (threadIdx.x >> 5);
    int lane = threadIdx.x & 31;
    if (row >= rows) return;
    const float* p = a + (size_t)row * D_DIM;
    float acc = 0.0f;
#pragma unroll
    for (int i = 0; i < D_DIM / 32; i++) {
        float v = p[lane + 32 * i];
        acc = __fadd_rn(acc, __fmul_rn(v, v));   // separate roundings (no FMA)
    }
#pragma unroll
    for (int o = 16; o >= 1; o >>= 1)
        acc = __fadd_rn(acc, __shfl_down_sync(0xFFFFFFFFu, acc, o));
    if (lane == 0) out[row] = acc;
}

// ---------------------------------------------------------------------------
// Fused distance GEMM + argmin.
// d2(m,c) = fl( fl( x2[m] - 2*dot(x_m, e_c) ) + e2[c] )  -- matches reference
// formula x2 - 2*xe + e2 with left-to-right evaluation.
// Tie-break: smallest code index (jnp.argmin first-min semantics) via packed key.
__global__ __launch_bounds__(256, 2)
void dist_argmin_kernel(const float* __restrict__ X,
                        const float* __restrict__ E,
                        const float* __restrict__ x2,
                        const float* __restrict__ e2,
                        unsigned long long* __restrict__ best) {
    __shared__ float As[TK][TM + 4];
    __shared__ float Bs[TK][TC + 4];

    const int m0 = blockIdx.y * TM;
    const int c0 = blockIdx.x * TC;
    const int tid = threadIdx.x;
    const int tx = tid & 15;        // 16 threads across C
    const int ty = tid >> 4;        // 16 threads across M

    float acc[8][8];
#pragma unroll
    for (int i = 0; i < 8; i++)
#pragma unroll
        for (int j = 0; j < 8; j++) acc[i][j] = 0.0f;

    for (int k0 = 0; k0 < D_DIM; k0 += TK) {
        // Load tiles: 128 rows x 16 k each = 512 float4 per tile, 2 per thread.
#pragma unroll
        for (int l = 0; l < 2; l++) {
            int idx = tid + l * 256;      // 0..511
            int r   = idx >> 2;           // row within tile
            int f4  = idx & 3;            // which float4 in the 16-wide k chunk
            float4 va = *(const float4*)(X + (size_t)(m0 + r) * D_DIM + k0 + f4 * 4);
            As[f4 * 4 + 0][r] = va.x;
            As[f4 * 4 + 1][r] = va.y;
            As[f4 * 4 + 2][r] = va.z;
            As[f4 * 4 + 3][r] = va.w;
            float4 vb = *(const float4*)(E + (size_t)(c0 + r) * D_DIM + k0 + f4 * 4);
            Bs[f4 * 4 + 0][r] = vb.x;
            Bs[f4 * 4 + 1][r] = vb.y;
            Bs[f4 * 4 + 2][r] = vb.z;
            Bs[f4 * 4 + 3][r] = vb.w;
        }
        __syncthreads();
#pragma unroll
        for (int kk = 0; kk < TK; kk++) {
            float ra[8], rb[8];
            float4 a0 = *(const float4*)&As[kk][ty * 8 + 0];
            float4 a1 = *(const float4*)&As[kk][ty * 8 + 4];
            ra[0]=a0.x; ra[1]=a0.y; ra[2]=a0.z; ra[3]=a0.w;
            ra[4]=a1.x; ra[5]=a1.y; ra[6]=a1.z; ra[7]=a1.w;
            float4 b0 = *(const float4*)&Bs[kk][tx * 8 + 0];
            float4 b1 = *(const float4*)&Bs[kk][tx * 8 + 4];
            rb[0]=b0.x; rb[1]=b0.y; rb[2]=b0.z; rb[3]=b0.w;
            rb[4]=b1.x; rb[5]=b1.y; rb[6]=b1.z; rb[7]=b1.w;
#pragma unroll
            for (int i = 0; i < 8; i++)
#pragma unroll
                for (int j = 0; j < 8; j++)
                    acc[i][j] = __fmaf_rn(ra[i], rb[j], acc[i][j]);
        }
        __syncthreads();
    }

    // Epilogue: d2 + argmin over this C-tile, reduce, atomic combine.
    float rx2[8], re2[8];
#pragma unroll
    for (int i = 0; i < 8; i++) rx2[i] = x2[m0 + ty * 8 + i];
#pragma unroll
    for (int j = 0; j < 8; j++) re2[j] = e2[c0 + tx * 8 + j];

#pragma unroll
    for (int i = 0; i < 8; i++) {
        unsigned long long kbest = 0xFFFFFFFFFFFFFFFFull;
#pragma unroll
        for (int j = 0; j < 8; j++) {
            // t = x2 - 2*dot (one rounding; -2*dot is exact), then + e2 (one rounding)
            float t  = __fadd_rn(rx2[i], -2.0f * acc[i][j]);
            float d2 = __fadd_rn(t, re2[j]);
            unsigned long long key =
                ((unsigned long long)__float_as_uint(d2) << 32) |
                (unsigned int)(c0 + tx * 8 + j);
            kbest = (key < kbest) ? key : kbest;
        }
        // reduce across the 16 tx lanes (each half-warp is one ty group)
#pragma unroll
        for (int o = 1; o < 16; o <<= 1) {
            unsigned long long other = __shfl_xor_sync(0xFFFFFFFFu, kbest, o);
            kbest = (other < kbest) ? other : kbest;
        }
        if (tx == 0) atomicMin(&best[m0 + ty * 8 + i], kbest);
    }
}

// ---------------------------------------------------------------------------
// Gather quantize rows + write indices (as float, after the quantize block).
__global__ void finalize_kernel(const float* __restrict__ E,
                                const unsigned long long* __restrict__ best,
                                float* __restrict__ out_q,
                                float* __restrict__ out_ind,
                                int write_ind) {
    int row = blockIdx.x * (blockDim.x >> 5) + (threadIdx.x >> 5);
    int lane = threadIdx.x & 31;
    if (row >= M_PTS) return;
    unsigned int idx = (unsigned int)(best[row] & 0xFFFFFFFFu);
    const float4* src = (const float4*)(E + (size_t)idx * D_DIM);
    float4* dst = (float4*)(out_q + (size_t)row * D_DIM);
    dst[lane]      = src[lane];
    dst[lane + 32] = src[lane + 32];
    if (write_ind && lane == 0) out_ind[row] = (float)idx;
}

// ---------------------------------------------------------------------------
extern "C" void kernel_launch(void* const* d_in, const int* in_sizes, int n_in,
                              void* d_out, int out_size) {
    // Robust input binding by element count: x = 4,194,304; embed = 2,097,152.
    const float* X = (const float*)d_in[0];
    const float* E = (const float*)d_in[1];
    if (n_in >= 2 && in_sizes[0] == C_CODES * D_DIM && in_sizes[1] == M_PTS * D_DIM) {
        X = (const float*)d_in[1];
        E = (const float*)d_in[0];
    }

    float* out_q = (float*)d_out;
    int write_ind = (out_size >= M_PTS * D_DIM + M_PTS) ? 1 : 0;
    float* out_ind = out_q + (size_t)M_PTS * D_DIM;

    unsigned long long* best;
    float *x2p, *e2p;
    cudaGetSymbolAddress((void**)&best, g_best);
    cudaGetSymbolAddress((void**)&x2p, g_x2);
    cudaGetSymbolAddress((void**)&e2p, g_e2);

    init_best_kernel<<<(M_PTS + 255) / 256, 256>>>(best, M_PTS);
    rowsumsq_kernel<<<(M_PTS + 7) / 8, 256>>>(X, x2p, M_PTS);
    rowsumsq_kernel<<<(C_CODES + 7) / 8, 256>>>(E, e2p, C_CODES);

    dim3 grid(C_CODES / TC, M_PTS / TM);
    dist_argmin_kernel<<<grid, 256>>>(X, E, x2p, e2p, best);

    finalize_kernel<<<(M_PTS + 7) / 8, 256>>>(E, best, out_q, out_ind, write_ind);
}

// round 3
// speedup vs baseline: 2.3017x; 2.3017x over previous
#include <cuda_runtime.h>
#include <cuda_fp16.h>
#include <stdint.h>

typedef unsigned long long ull;
typedef unsigned int u32;

#define M_PTS 16384
#define D_DIM 256
#define C_CODES 8192

#define BM 128
#define BN 256
#define BK 32
#define NKB (D_DIM / BK)          // 8 k-chunks
#define STRIDE 40                 // halfs per row in smem (padded, conflict-free)
#define STAGE_HALFS ((BM * 2 + BN * 2) * STRIDE)   // Ah,Am,Bh,Bm = 30720
#define STAGE_BYTES (STAGE_HALFS * 2)              // 61440
#define SMEM_TOTAL (2 * STAGE_BYTES + BN * 4)      // + e2 staging = 123904

// smem offsets within a stage (halfs)
#define OFF_AH 0
#define OFF_AM (BM * STRIDE)                       // 5120
#define OFF_BH (2 * BM * STRIDE)                   // 10240
#define OFF_BM (2 * BM * STRIDE + BN * STRIDE)     // 20480

// ---------------------------------------------------------------------------
// Static scratch (no cudaMalloc allowed). Row-major [row][256] half arrays.
__device__ __align__(16) __half g_Ah[M_PTS * D_DIM];
__device__ __align__(16) __half g_Am[M_PTS * D_DIM];
__device__ __align__(16) __half g_Bh[C_CODES * D_DIM];
__device__ __align__(16) __half g_Bm[C_CODES * D_DIM];
__device__ ull   g_best[M_PTS];
__device__ float g_x2[M_PTS];
__device__ float g_e2[C_CODES];

// ---------------------------------------------------------------------------
__device__ __forceinline__ u32 smem_u32(const void* p) {
    u32 a;
    asm("{ .reg .u64 t; cvta.to.shared.u64 t, %1; cvt.u32.u64 %0, t; }" : "=r"(a) : "l"(p));
    return a;
}
__device__ __forceinline__ void cp16(u32 dst, const void* src) {
    asm volatile("cp.async.cg.shared.global [%0], [%1], 16;" :: "r"(dst), "l"(src));
}
__device__ __forceinline__ void cp_commit() {
    asm volatile("cp.async.commit_group;" ::: "memory");
}
template <int N>
__device__ __forceinline__ void cp_wait() {
    asm volatile("cp.async.wait_group %0;" :: "n"(N) : "memory");
}
__device__ __forceinline__ void mma16816(float* c, u32 a0, u32 a1, u32 a2, u32 a3,
                                         u32 b0, u32 b1) {
    asm volatile(
        "mma.sync.aligned.m16n8k16.row.col.f32.f16.f16.f32 "
        "{%0,%1,%2,%3}, {%4,%5,%6,%7}, {%8,%9}, {%0,%1,%2,%3};"
        : "+f"(c[0]), "+f"(c[1]), "+f"(c[2]), "+f"(c[3])
        : "r"(a0), "r"(a1), "r"(a2), "r"(a3), "r"(b0), "r"(b1));
}

// ---------------------------------------------------------------------------
__global__ void init_best_kernel(ull* best, int n) {
    int i = blockIdx.x * blockDim.x + threadIdx.x;
    if (i < n) best[i] = 0xFFFFFFFFFFFFFFFFull;
}

// row sum of squares (exact recipe that gave rel_err == 0 in round 1)
__global__ void rowsumsq_kernel(const float* __restrict__ a, float* __restrict__ out, int rows) {
    int row = blockIdx.x * (blockDim.x >> 5) + (threadIdx.x >> 5);
    int lane = threadIdx.x & 31;
    if (row >= rows) return;
    const float* p = a + (size_t)row * D_DIM;
    float acc = 0.0f;
#pragma unroll
    for (int i = 0; i < D_DIM / 32; i++) {
        float v = p[lane + 32 * i];
        acc = __fadd_rn(acc, __fmul_rn(v, v));
    }
#pragma unroll
    for (int o = 16; o >= 1; o >>= 1)
        acc = __fadd_rn(acc, __shfl_down_sync(0xFFFFFFFFu, acc, o));
    if (lane == 0) out[row] = acc;
}

// fp32 -> (hi fp16, mid fp16), row-major output. scale is a power of two (exact).
__global__ void split_kernel(const float* __restrict__ src, __half* __restrict__ dh,
                             __half* __restrict__ dm, int rows, float scale) {
    int idx = blockIdx.x * blockDim.x + threadIdx.x;   // one float4 per thread
    if (idx >= rows * (D_DIM / 4)) return;
    int row = idx >> 6;
    int q = idx & 63;
    float4 v = ((const float4*)(src + (size_t)row * D_DIM))[q];

    float s0 = v.x * scale, s1 = v.y * scale, s2 = v.z * scale, s3 = v.w * scale;
    __half h0 = __float2half_rn(s0), h1 = __float2half_rn(s1);
    __half h2 = __float2half_rn(s2), h3 = __float2half_rn(s3);
    __half m0 = __float2half_rn(s0 - __half2float(h0));
    __half m1 = __float2half_rn(s1 - __half2float(h1));
    __half m2 = __float2half_rn(s2 - __half2float(h2));
    __half m3 = __float2half_rn(s3 - __half2float(h3));

    __half2 hh0 = __halves2half2(h0, h1), hh1 = __halves2half2(h2, h3);
    __half2 mm0 = __halves2half2(m0, m1), mm1 = __halves2half2(m2, m3);
    uint2 hp, mp;
    hp.x = *(u32*)&hh0; hp.y = *(u32*)&hh1;
    mp.x = *(u32*)&mm0; mp.y = *(u32*)&mm1;
    *(uint2*)(dh + (size_t)row * D_DIM + q * 4) = hp;
    *(uint2*)(dm + (size_t)row * D_DIM + q * 4) = mp;
}

// ---------------------------------------------------------------------------
// Fused fp16-split HMMA GEMM + argmin. Grid (C/BN=32, M/BM=128), 256 thr.
__global__ __launch_bounds__(256, 1)
void vq_hmma_kernel(const float* __restrict__ x2g, const float* __restrict__ e2g,
                    ull* __restrict__ best) {
    extern __shared__ __half smh[];
    const u32 sb = smem_u32(smh);
    const int tid = threadIdx.x;
    const int lane = tid & 31;
    const int wid = tid >> 5;
    const int warp_m = wid >> 2;      // 0..1
    const int warp_n = wid & 3;       // 0..3

    const int mrow0 = blockIdx.y * BM;
    const int crow0 = blockIdx.x * BN;

    float* e2s = (float*)((char*)smh + 2 * STAGE_BYTES);
    e2s[tid] = e2g[crow0 + tid];      // BN == blockDim.x == 256

    // ---- cp.async stage loader: 3072 16B tasks, 12 per thread ----
    auto issue = [&](int kb) {
        u32 sbase = sb + (u32)(kb & 1) * STAGE_BYTES;
        int kcol = kb * BK;
#pragma unroll
        for (int i = 0; i < 12; i++) {
            int t = tid + i * 256;
            if (t < 1024) {
                int split = t >> 9, r = (t >> 2) & 127, c = t & 3;
                const __half* g = (split ? g_Am : g_Ah) +
                                  (size_t)(mrow0 + r) * D_DIM + kcol + c * 8;
                u32 s = sbase + (u32)((split ? OFF_AM : OFF_AH) + r * STRIDE + c * 8) * 2;
                cp16(s, g);
            } else {
                int t2 = t - 1024;
                int split = t2 >> 10, r = (t2 >> 2) & 255, c = t2 & 3;
                const __half* g = (split ? g_Bm : g_Bh) +
                                  (size_t)(crow0 + r) * D_DIM + kcol + c * 8;
                u32 s = sbase + (u32)((split ? OFF_BM : OFF_BH) + r * STRIDE + c * 8) * 2;
                cp16(s, g);
            }
        }
        cp_commit();
    };

    float acc[4][8][4];
#pragma unroll
    for (int mt = 0; mt < 4; mt++)
#pragma unroll
        for (int nt = 0; nt < 8; nt++)
#pragma unroll
            for (int r = 0; r < 4; r++) acc[mt][nt][r] = 0.0f;

    issue(0);

    const int a_row = warp_m * 64 + (lane >> 2);   // + mt*16 (+8)
    const int b_row = warp_n * 64 + (lane >> 2);   // + nt*8
    const int k_off = (lane & 3) * 2;

    for (int kb = 0; kb < NKB; kb++) {
        if (kb + 1 < NKB) issue(kb + 1);
        if (kb + 1 < NKB) cp_wait<1>(); else cp_wait<0>();
        __syncthreads();

        const __half* st = smh + (kb & 1) * STAGE_HALFS;
#pragma unroll
        for (int ks = 0; ks < 2; ks++) {
            const int kc = ks * 16 + k_off;
            u32 af[4][4], bh[8][2], bm[8][2];
#pragma unroll
            for (int mt = 0; mt < 4; mt++) {
                const __half* p = st + OFF_AH + (a_row + mt * 16) * STRIDE + kc;
                af[mt][0] = *(const u32*)p;
                af[mt][1] = *(const u32*)(p + 8 * STRIDE);
                af[mt][2] = *(const u32*)(p + 8);
                af[mt][3] = *(const u32*)(p + 8 * STRIDE + 8);
            }
#pragma unroll
            for (int nt = 0; nt < 8; nt++) {
                const __half* p = st + OFF_BH + (b_row + nt * 8) * STRIDE + kc;
                bh[nt][0] = *(const u32*)p;
                bh[nt][1] = *(const u32*)(p + 8);
                const __half* q = st + OFF_BM + (b_row + nt * 8) * STRIDE + kc;
                bm[nt][0] = *(const u32*)q;
                bm[nt][1] = *(const u32*)(q + 8);
            }
#pragma unroll
            for (int mt = 0; mt < 4; mt++)
#pragma unroll
                for (int nt = 0; nt < 8; nt++)
                    mma16816(acc[mt][nt], af[mt][0], af[mt][1], af[mt][2], af[mt][3],
                             bh[nt][0], bh[nt][1]);
#pragma unroll
            for (int mt = 0; mt < 4; mt++)
#pragma unroll
                for (int nt = 0; nt < 8; nt++)
                    mma16816(acc[mt][nt], af[mt][0], af[mt][1], af[mt][2], af[mt][3],
                             bm[nt][0], bm[nt][1]);
            // reuse af regs for Am
#pragma unroll
            for (int mt = 0; mt < 4; mt++) {
                const __half* p = st + OFF_AM + (a_row + mt * 16) * STRIDE + kc;
                af[mt][0] = *(const u32*)p;
                af[mt][1] = *(const u32*)(p + 8 * STRIDE);
                af[mt][2] = *(const u32*)(p + 8);
                af[mt][3] = *(const u32*)(p + 8 * STRIDE + 8);
            }
#pragma unroll
            for (int mt = 0; mt < 4; mt++)
#pragma unroll
                for (int nt = 0; nt < 8; nt++)
                    mma16816(acc[mt][nt], af[mt][0], af[mt][1], af[mt][2], af[mt][3],
                             bh[nt][0], bh[nt][1]);
        }
        __syncthreads();
    }

    // ---- epilogue: d2 + argmin ----
    const float inv = 3.0517578125e-05f;   // 2^-15 (exact)
#pragma unroll
    for (int mt = 0; mt < 4; mt++) {
#pragma unroll
        for (int rh = 0; rh < 2; rh++) {
            int m = mrow0 + warp_m * 64 + mt * 16 + (lane >> 2) + rh * 8;
            float x2v = x2g[m];
            ull kbest = 0xFFFFFFFFFFFFFFFFull;
#pragma unroll
            for (int nt = 0; nt < 8; nt++) {
#pragma unroll
                for (int cc = 0; cc < 2; cc++) {
                    int cl = warp_n * 64 + nt * 8 + (lane & 3) * 2 + cc;
                    float xe2 = acc[mt][nt][rh * 2 + cc] * inv;  // = 2*xe, exact scale
                    float t = __fadd_rn(x2v, -xe2);
                    float d2 = __fadd_rn(t, e2s[cl]);
                    ull key = ((ull)__float_as_uint(d2) << 32) | (u32)(crow0 + cl);
                    kbest = (key < kbest) ? key : kbest;
                }
            }
            ull o1 = __shfl_xor_sync(0xFFFFFFFFu, kbest, 1);
            kbest = (o1 < kbest) ? o1 : kbest;
            ull o2 = __shfl_xor_sync(0xFFFFFFFFu, kbest, 2);
            kbest = (o2 < kbest) ? o2 : kbest;
            if ((lane & 3) == 0) atomicMin(&best[m], kbest);
        }
    }
}

// ---------------------------------------------------------------------------
__global__ void finalize_kernel(const float* __restrict__ E,
                                const ull* __restrict__ best,
                                float* __restrict__ out_q,
                                float* __restrict__ out_ind, int write_ind) {
    int row = blockIdx.x * (blockDim.x >> 5) + (threadIdx.x >> 5);
    int lane = threadIdx.x & 31;
    if (row >= M_PTS) return;
    u32 idx = (u32)(best[row] & 0xFFFFFFFFu);
    const float4* src = (const float4*)(E + (size_t)idx * D_DIM);
    float4* dst = (float4*)(out_q + (size_t)row * D_DIM);
    dst[lane]      = src[lane];
    dst[lane + 32] = src[lane + 32];
    if (write_ind && lane == 0) out_ind[row] = (float)idx;
}

// ---------------------------------------------------------------------------
extern "C" void kernel_launch(void* const* d_in, const int* in_sizes, int n_in,
                              void* d_out, int out_size) {
    const float* X = (const float*)d_in[0];
    const float* E = (const float*)d_in[1];
    if (n_in >= 2 && in_sizes[0] == C_CODES * D_DIM && in_sizes[1] == M_PTS * D_DIM) {
        X = (const float*)d_in[1];
        E = (const float*)d_in[0];
    }

    float* out_q = (float*)d_out;
    int write_ind = (out_size >= M_PTS * D_DIM + M_PTS) ? 1 : 0;
    float* out_ind = out_q + (size_t)M_PTS * D_DIM;

    ull* best; float *x2p, *e2p; __half *ah, *am, *bh, *bm;
    cudaGetSymbolAddress((void**)&best, g_best);
    cudaGetSymbolAddress((void**)&x2p, g_x2);
    cudaGetSymbolAddress((void**)&e2p, g_e2);
    cudaGetSymbolAddress((void**)&ah, g_Ah);
    cudaGetSymbolAddress((void**)&am, g_Am);
    cudaGetSymbolAddress((void**)&bh, g_Bh);
    cudaGetSymbolAddress((void**)&bm, g_Bm);

    init_best_kernel<<<(M_PTS + 255) / 256, 256>>>(best, M_PTS);
    rowsumsq_kernel<<<(M_PTS + 7) / 8, 256>>>(X, x2p, M_PTS);
    rowsumsq_kernel<<<(C_CODES + 7) / 8, 256>>>(E, e2p, C_CODES);

    split_kernel<<<(M_PTS * 64 + 255) / 256, 256>>>(X, ah, am, M_PTS, 1.0f);
    split_kernel<<<(C_CODES * 64 + 255) / 256, 256>>>(E, bh, bm, C_CODES, 65536.0f);

    cudaFuncSetAttribute(vq_hmma_kernel, cudaFuncAttributeMaxDynamicSharedMemorySize,
                         SMEM_TOTAL);
    dim3 grid(C_CODES / BN, M_PTS / BM);
    vq_hmma_kernel<<<grid, 256, SMEM_TOTAL>>>(x2p, e2p, best);

    finalize_kernel<<<(M_PTS + 7) / 8, 256>>>(E, best, out_q, out_ind, write_ind);
}

// round 4
// speedup vs baseline: 2.3360x; 1.0149x over previous
#include <cuda_runtime.h>
#include <cuda_fp16.h>
#include <stdint.h>

typedef unsigned long long ull;
typedef unsigned int u32;

#define M_PTS 16384
#define D_DIM 256
#define C_CODES 8192

#define BM 128
#define BN 256
#define BK 32
#define NKB (D_DIM / BK)          // 8 k-chunks
#define STRIDE 40                 // halfs per row in smem (padded, conflict-free)
#define STAGE_HALFS ((BM * 2 + BN * 2) * STRIDE)   // Ah,Am,Bh,Bm = 30720
#define STAGE_BYTES (STAGE_HALFS * 2)              // 61440
#define SMEM_TOTAL (2 * STAGE_BYTES + BN * 4)      // + e2 staging = 123904

// smem offsets within a stage (halfs)
#define OFF_AH 0
#define OFF_AM (BM * STRIDE)                       // 5120
#define OFF_BH (2 * BM * STRIDE)                   // 10240
#define OFF_BM (2 * BM * STRIDE + BN * STRIDE)     // 20480

#define AM_DELTA (OFF_AM * 2)                      // bytes between Ah and Am
#define BM_DELTA (BN * STRIDE * 2)                 // bytes between Bh and Bm

// ---------------------------------------------------------------------------
// Static scratch (no cudaMalloc allowed). Row-major [row][256] half arrays.
__device__ __align__(16) __half g_Ah[M_PTS * D_DIM];
__device__ __align__(16) __half g_Am[M_PTS * D_DIM];
__device__ __align__(16) __half g_Bh[C_CODES * D_DIM];
__device__ __align__(16) __half g_Bm[C_CODES * D_DIM];
__device__ ull   g_best[M_PTS];
__device__ float g_x2[M_PTS];
__device__ float g_e2[C_CODES];

// ---------------------------------------------------------------------------
__device__ __forceinline__ u32 smem_u32(const void* p) {
    u32 a;
    asm("{ .reg .u64 t; cvta.to.shared.u64 t, %1; cvt.u32.u64 %0, t; }" : "=r"(a) : "l"(p));
    return a;
}
__device__ __forceinline__ void cp16(u32 dst, const void* src) {
    asm volatile("cp.async.cg.shared.global [%0], [%1], 16;" :: "r"(dst), "l"(src));
}
__device__ __forceinline__ void cp_commit() {
    asm volatile("cp.async.commit_group;" ::: "memory");
}
template <int N>
__device__ __forceinline__ void cp_wait() {
    asm volatile("cp.async.wait_group %0;" :: "n"(N) : "memory");
}
__device__ __forceinline__ void mma16816(float* c, u32 a0, u32 a1, u32 a2, u32 a3,
                                         u32 b0, u32 b1) {
    asm volatile(
        "mma.sync.aligned.m16n8k16.row.col.f32.f16.f16.f32 "
        "{%0,%1,%2,%3}, {%4,%5,%6,%7}, {%8,%9}, {%0,%1,%2,%3};"
        : "+f"(c[0]), "+f"(c[1]), "+f"(c[2]), "+f"(c[3])
        : "r"(a0), "r"(a1), "r"(a2), "r"(a3), "r"(b0), "r"(b1));
}
__device__ __forceinline__ void ldsm_x4(u32* r, u32 addr) {
    asm volatile("ldmatrix.sync.aligned.m8n8.x4.shared.b16 {%0,%1,%2,%3}, [%4];"
                 : "=r"(r[0]), "=r"(r[1]), "=r"(r[2]), "=r"(r[3]) : "r"(addr));
}

// ---------------------------------------------------------------------------
__global__ void init_best_kernel(ull* best, int n) {
    int i = blockIdx.x * blockDim.x + threadIdx.x;
    if (i < n) best[i] = 0xFFFFFFFFFFFFFFFFull;
}

// row sum of squares (exact recipe that gave rel_err == 0 in round 1)
__global__ void rowsumsq_kernel(const float* __restrict__ a, float* __restrict__ out, int rows) {
    int row = blockIdx.x * (blockDim.x >> 5) + (threadIdx.x >> 5);
    int lane = threadIdx.x & 31;
    if (row >= rows) return;
    const float* p = a + (size_t)row * D_DIM;
    float acc = 0.0f;
#pragma unroll
    for (int i = 0; i < D_DIM / 32; i++) {
        float v = p[lane + 32 * i];
        acc = __fadd_rn(acc, __fmul_rn(v, v));
    }
#pragma unroll
    for (int o = 16; o >= 1; o >>= 1)
        acc = __fadd_rn(acc, __shfl_down_sync(0xFFFFFFFFu, acc, o));
    if (lane == 0) out[row] = acc;
}

// fp32 -> (hi fp16, mid fp16), row-major output. scale is a power of two (exact).
__global__ void split_kernel(const float* __restrict__ src, __half* __restrict__ dh,
                             __half* __restrict__ dm, int rows, float scale) {
    int idx = blockIdx.x * blockDim.x + threadIdx.x;   // one float4 per thread
    if (idx >= rows * (D_DIM / 4)) return;
    int row = idx >> 6;
    int q = idx & 63;
    float4 v = ((const float4*)(src + (size_t)row * D_DIM))[q];

    float s0 = v.x * scale, s1 = v.y * scale, s2 = v.z * scale, s3 = v.w * scale;
    __half h0 = __float2half_rn(s0), h1 = __float2half_rn(s1);
    __half h2 = __float2half_rn(s2), h3 = __float2half_rn(s3);
    __half m0 = __float2half_rn(s0 - __half2float(h0));
    __half m1 = __float2half_rn(s1 - __half2float(h1));
    __half m2 = __float2half_rn(s2 - __half2float(h2));
    __half m3 = __float2half_rn(s3 - __half2float(h3));

    __half2 hh0 = __halves2half2(h0, h1), hh1 = __halves2half2(h2, h3);
    __half2 mm0 = __halves2half2(m0, m1), mm1 = __halves2half2(m2, m3);
    uint2 hp, mp;
    hp.x = *(u32*)&hh0; hp.y = *(u32*)&hh1;
    mp.x = *(u32*)&mm0; mp.y = *(u32*)&mm1;
    *(uint2*)(dh + (size_t)row * D_DIM + q * 4) = hp;
    *(uint2*)(dm + (size_t)row * D_DIM + q * 4) = mp;
}

// ---------------------------------------------------------------------------
// Fused fp16-split HMMA GEMM + argmin. Grid (C/BN=32, M/BM=128), 256 thr.
__global__ __launch_bounds__(256, 1)
void vq_hmma_kernel(const float* __restrict__ x2g, const float* __restrict__ e2g,
                    ull* __restrict__ best) {
    extern __shared__ __half smh[];
    const u32 sb = smem_u32(smh);
    const int tid = threadIdx.x;
    const int lane = tid & 31;
    const int wid = tid >> 5;
    const int warp_m = wid >> 2;      // 0..1
    const int warp_n = wid & 3;       // 0..3

    const int mrow0 = blockIdx.y * BM;
    const int crow0 = blockIdx.x * BN;

    float* e2s = (float*)((char*)smh + 2 * STAGE_BYTES);
    e2s[tid] = e2g[crow0 + tid];      // BN == blockDim.x == 256

    // ---- cp.async stage loader: 3072 16B tasks, 12 per thread ----
    auto issue = [&](int kb) {
        u32 sbase = sb + (u32)(kb & 1) * STAGE_BYTES;
        int kcol = kb * BK;
#pragma unroll
        for (int i = 0; i < 12; i++) {
            int t = tid + i * 256;
            if (t < 1024) {
                int split = t >> 9, r = (t >> 2) & 127, c = t & 3;
                const __half* g = (split ? g_Am : g_Ah) +
                                  (size_t)(mrow0 + r) * D_DIM + kcol + c * 8;
                u32 s = sbase + (u32)((split ? OFF_AM : OFF_AH) + r * STRIDE + c * 8) * 2;
                cp16(s, g);
            } else {
                int t2 = t - 1024;
                int split = t2 >> 10, r = (t2 >> 2) & 255, c = t2 & 3;
                const __half* g = (split ? g_Bm : g_Bh) +
                                  (size_t)(crow0 + r) * D_DIM + kcol + c * 8;
                u32 s = sbase + (u32)((split ? OFF_BM : OFF_BH) + r * STRIDE + c * 8) * 2;
                cp16(s, g);
            }
        }
        cp_commit();
    };

    float acc[4][8][4];
#pragma unroll
    for (int mt = 0; mt < 4; mt++)
#pragma unroll
        for (int nt = 0; nt < 8; nt++)
#pragma unroll
            for (int r = 0; r < 4; r++) acc[mt][nt][r] = 0.0f;

    issue(0);

    // ---- per-lane ldmatrix base offsets (bytes, relative to stage base) ----
    // A x4 tile (16x16): groups g=lane/8 -> {m0k0, m8k0, m0k8, m8k8}
    const int a_r = (lane & 7) + ((lane >> 3) & 1) * 8;
    const int a_k = (lane >> 4) * 8;
    // B x4 covers an nt-pair: g -> {ntEven k0, ntEven k8, ntOdd k0, ntOdd k8}
    const int b_r = (lane & 7) + (lane >> 4) * 8;
    const int b_k = ((lane >> 3) & 1) * 8;

    u32 aoff[4], boff[4];
#pragma unroll
    for (int mt = 0; mt < 4; mt++)
        aoff[mt] = (u32)((OFF_AH + (warp_m * 64 + mt * 16 + a_r) * STRIDE + a_k) * 2);
#pragma unroll
    for (int p = 0; p < 4; p++)
        boff[p] = (u32)((OFF_BH + (warp_n * 64 + p * 16 + b_r) * STRIDE + b_k) * 2);

    for (int kb = 0; kb < NKB; kb++) {
        if (kb + 1 < NKB) issue(kb + 1);
        if (kb + 1 < NKB) cp_wait<1>(); else cp_wait<0>();
        __syncthreads();

        const u32 sbase = sb + (u32)(kb & 1) * STAGE_BYTES;
#pragma unroll
        for (int ks = 0; ks < 2; ks++) {
            const u32 kbyte = (u32)(ks * 32);   // 16 halfs
            u32 af[4][4], bhf[4][4], bmf[4][4];
#pragma unroll
            for (int mt = 0; mt < 4; mt++) ldsm_x4(af[mt], sbase + aoff[mt] + kbyte);
#pragma unroll
            for (int p = 0; p < 4; p++) ldsm_x4(bhf[p], sbase + boff[p] + kbyte);
#pragma unroll
            for (int p = 0; p < 4; p++) ldsm_x4(bmf[p], sbase + boff[p] + BM_DELTA + kbyte);

#pragma unroll
            for (int mt = 0; mt < 4; mt++)
#pragma unroll
                for (int nt = 0; nt < 8; nt++) {
                    const u32* bf = bhf[nt >> 1];
                    int o = (nt & 1) * 2;
                    mma16816(acc[mt][nt], af[mt][0], af[mt][1], af[mt][2], af[mt][3],
                             bf[o], bf[o + 1]);
                }
#pragma unroll
            for (int mt = 0; mt < 4; mt++)
#pragma unroll
                for (int nt = 0; nt < 8; nt++) {
                    const u32* bf = bmf[nt >> 1];
                    int o = (nt & 1) * 2;
                    mma16816(acc[mt][nt], af[mt][0], af[mt][1], af[mt][2], af[mt][3],
                             bf[o], bf[o + 1]);
                }
            // reuse af regs for Am
#pragma unroll
            for (int mt = 0; mt < 4; mt++) ldsm_x4(af[mt], sbase + aoff[mt] + AM_DELTA + kbyte);
#pragma unroll
            for (int mt = 0; mt < 4; mt++)
#pragma unroll
                for (int nt = 0; nt < 8; nt++) {
                    const u32* bf = bhf[nt >> 1];
                    int o = (nt & 1) * 2;
                    mma16816(acc[mt][nt], af[mt][0], af[mt][1], af[mt][2], af[mt][3],
                             bf[o], bf[o + 1]);
                }
        }
        __syncthreads();
    }

    // ---- epilogue: d2 + argmin ----
    const float inv = 3.0517578125e-05f;   // 2^-15 (exact)
#pragma unroll
    for (int mt = 0; mt < 4; mt++) {
#pragma unroll
        for (int rh = 0; rh < 2; rh++) {
            int m = mrow0 + warp_m * 64 + mt * 16 + (lane >> 2) + rh * 8;
            float x2v = x2g[m];
            ull kbest = 0xFFFFFFFFFFFFFFFFull;
#pragma unroll
            for (int nt = 0; nt < 8; nt++) {
#pragma unroll
                for (int cc = 0; cc < 2; cc++) {
                    int cl = warp_n * 64 + nt * 8 + (lane & 3) * 2 + cc;
                    float xe2 = acc[mt][nt][rh * 2 + cc] * inv;  // = 2*xe, exact scale
                    float t = __fadd_rn(x2v, -xe2);
                    float d2 = __fadd_rn(t, e2s[cl]);
                    ull key = ((ull)__float_as_uint(d2) << 32) | (u32)(crow0 + cl);
                    kbest = (key < kbest) ? key : kbest;
                }
            }
            ull o1 = __shfl_xor_sync(0xFFFFFFFFu, kbest, 1);
            kbest = (o1 < kbest) ? o1 : kbest;
            ull o2 = __shfl_xor_sync(0xFFFFFFFFu, kbest, 2);
            kbest = (o2 < kbest) ? o2 : kbest;
            if ((lane & 3) == 0) atomicMin(&best[m], kbest);
        }
    }
}

// ---------------------------------------------------------------------------
__global__ void finalize_kernel(const float* __restrict__ E,
                                const ull* __restrict__ best,
                                float* __restrict__ out_q,
                                float* __restrict__ out_ind, int write_ind) {
    int row = blockIdx.x * (blockDim.x >> 5) + (threadIdx.x >> 5);
    int lane = threadIdx.x & 31;
    if (row >= M_PTS) return;
    u32 idx = (u32)(best[row] & 0xFFFFFFFFu);
    const float4* src = (const float4*)(E + (size_t)idx * D_DIM);
    float4* dst = (float4*)(out_q + (size_t)row * D_DIM);
    dst[lane]      = src[lane];
    dst[lane + 32] = src[lane + 32];
    if (write_ind && lane == 0) out_ind[row] = (float)idx;
}

// ---------------------------------------------------------------------------
extern "C" void kernel_launch(void* const* d_in, const int* in_sizes, int n_in,
                              void* d_out, int out_size) {
    const float* X = (const float*)d_in[0];
    const float* E = (const float*)d_in[1];
    if (n_in >= 2 && in_sizes[0] == C_CODES * D_DIM && in_sizes[1] == M_PTS * D_DIM) {
        X = (const float*)d_in[1];
        E = (const float*)d_in[0];
    }

    float* out_q = (float*)d_out;
    int write_ind = (out_size >= M_PTS * D_DIM + M_PTS) ? 1 : 0;
    float* out_ind = out_q + (size_t)M_PTS * D_DIM;

    ull* best; float *x2p, *e2p; __half *ah, *am, *bh, *bm;
    cudaGetSymbolAddress((void**)&best, g_best);
    cudaGetSymbolAddress((void**)&x2p, g_x2);
    cudaGetSymbolAddress((void**)&e2p, g_e2);
    cudaGetSymbolAddress((void**)&ah, g_Ah);
    cudaGetSymbolAddress((void**)&am, g_Am);
    cudaGetSymbolAddress((void**)&bh, g_Bh);
    cudaGetSymbolAddress((void**)&bm, g_Bm);

    init_best_kernel<<<(M_PTS + 255) / 256, 256>>>(best, M_PTS);
    rowsumsq_kernel<<<(M_PTS + 7) / 8, 256>>>(X, x2p, M_PTS);
    rowsumsq_kernel<<<(C_CODES + 7) / 8, 256>>>(E, e2p, C_CODES);

    split_kernel<<<(M_PTS * 64 + 255) / 256, 256>>>(X, ah, am, M_PTS, 1.0f);
    split_kernel<<<(C_CODES * 64 + 255) / 256, 256>>>(E, bh, bm, C_CODES, 65536.0f);

    cudaFuncSetAttribute(vq_hmma_kernel, cudaFuncAttributeMaxDynamicSharedMemorySize,
                         SMEM_TOTAL);
    dim3 grid(C_CODES / BN, M_PTS / BM);
    vq_hmma_kernel<<<grid, 256, SMEM_TOTAL>>>(x2p, e2p, best);

    finalize_kernel<<<(M_PTS + 7) / 8, 256>>>(E, best, out_q, out_ind, write_ind);
}

// round 5
// speedup vs baseline: 2.5604x; 1.0960x over previous
#include <cuda_runtime.h>
#include <cuda_fp16.h>
#include <stdint.h>

typedef unsigned long long ull;
typedef unsigned int u32;

#define M_PTS 16384
#define D_DIM 256
#define C_CODES 8192

#define BM 128
#define BN 128
#define BK 32
#define NKB (D_DIM / BK)          // 8 k-chunks
#define STRIDE 40                 // halfs per row in smem (padded, conflict-free)
#define STAGE_HALFS ((BM * 2 + BN * 2) * STRIDE)   // Ah,Am,Bh,Bm = 20480
#define STAGE_BYTES (STAGE_HALFS * 2)              // 40960
#define SMEM_TOTAL (2 * STAGE_BYTES + BN * 4)      // + e2 staging = 82432

// smem offsets within a stage (halfs)
#define OFF_AH 0
#define OFF_AM (BM * STRIDE)                       // 5120
#define OFF_BH (2 * BM * STRIDE)                   // 10240
#define OFF_BM (2 * BM * STRIDE + BN * STRIDE)     // 15360

#define AM_DELTA (OFF_AM * 2)                      // bytes between Ah and Am
#define BM_DELTA (BN * STRIDE * 2)                 // bytes between Bh and Bm

// ---------------------------------------------------------------------------
// Static scratch (no cudaMalloc allowed). Row-major [row][256] half arrays.
__device__ __align__(16) __half g_Ah[M_PTS * D_DIM];
__device__ __align__(16) __half g_Am[M_PTS * D_DIM];
__device__ __align__(16) __half g_Bh[C_CODES * D_DIM];
__device__ __align__(16) __half g_Bm[C_CODES * D_DIM];
__device__ ull   g_best[M_PTS];
__device__ float g_x2[M_PTS];
__device__ float g_e2[C_CODES];

// ---------------------------------------------------------------------------
__device__ __forceinline__ u32 smem_u32(const void* p) {
    u32 a;
    asm("{ .reg .u64 t; cvta.to.shared.u64 t, %1; cvt.u32.u64 %0, t; }" : "=r"(a) : "l"(p));
    return a;
}
__device__ __forceinline__ void cp16(u32 dst, const void* src) {
    asm volatile("cp.async.cg.shared.global [%0], [%1], 16;" :: "r"(dst), "l"(src));
}
__device__ __forceinline__ void cp_commit() {
    asm volatile("cp.async.commit_group;" ::: "memory");
}
template <int N>
__device__ __forceinline__ void cp_wait() {
    asm volatile("cp.async.wait_group %0;" :: "n"(N) : "memory");
}
__device__ __forceinline__ void mma16816(float* c, u32 a0, u32 a1, u32 a2, u32 a3,
                                         u32 b0, u32 b1) {
    asm volatile(
        "mma.sync.aligned.m16n8k16.row.col.f32.f16.f16.f32 "
        "{%0,%1,%2,%3}, {%4,%5,%6,%7}, {%8,%9}, {%0,%1,%2,%3};"
        : "+f"(c[0]), "+f"(c[1]), "+f"(c[2]), "+f"(c[3])
        : "r"(a0), "r"(a1), "r"(a2), "r"(a3), "r"(b0), "r"(b1));
}
__device__ __forceinline__ void ldsm_x4(u32* r, u32 addr) {
    asm volatile("ldmatrix.sync.aligned.m8n8.x4.shared.b16 {%0,%1,%2,%3}, [%4];"
                 : "=r"(r[0]), "=r"(r[1]), "=r"(r[2]), "=r"(r[3]) : "r"(addr));
}

// ---------------------------------------------------------------------------
__global__ void init_best_kernel(ull* best, int n) {
    int i = blockIdx.x * blockDim.x + threadIdx.x;
    if (i < n) best[i] = 0xFFFFFFFFFFFFFFFFull;
}

// row sum of squares (exact recipe that gave rel_err == 0 in round 1)
__global__ void rowsumsq_kernel(const float* __restrict__ a, float* __restrict__ out, int rows) {
    int row = blockIdx.x * (blockDim.x >> 5) + (threadIdx.x >> 5);
    int lane = threadIdx.x & 31;
    if (row >= rows) return;
    const float* p = a + (size_t)row * D_DIM;
    float acc = 0.0f;
#pragma unroll
    for (int i = 0; i < D_DIM / 32; i++) {
        float v = p[lane + 32 * i];
        acc = __fadd_rn(acc, __fmul_rn(v, v));
    }
#pragma unroll
    for (int o = 16; o >= 1; o >>= 1)
        acc = __fadd_rn(acc, __shfl_down_sync(0xFFFFFFFFu, acc, o));
    if (lane == 0) out[row] = acc;
}

// fp32 -> (hi fp16, mid fp16), row-major output. scale is a power of two (exact).
__global__ void split_kernel(const float* __restrict__ src, __half* __restrict__ dh,
                             __half* __restrict__ dm, int rows, float scale) {
    int idx = blockIdx.x * blockDim.x + threadIdx.x;   // one float4 per thread
    if (idx >= rows * (D_DIM / 4)) return;
    int row = idx >> 6;
    int q = idx & 63;
    float4 v = ((const float4*)(src + (size_t)row * D_DIM))[q];

    float s0 = v.x * scale, s1 = v.y * scale, s2 = v.z * scale, s3 = v.w * scale;
    __half h0 = __float2half_rn(s0), h1 = __float2half_rn(s1);
    __half h2 = __float2half_rn(s2), h3 = __float2half_rn(s3);
    __half m0 = __float2half_rn(s0 - __half2float(h0));
    __half m1 = __float2half_rn(s1 - __half2float(h1));
    __half m2 = __float2half_rn(s2 - __half2float(h2));
    __half m3 = __float2half_rn(s3 - __half2float(h3));

    __half2 hh0 = __halves2half2(h0, h1), hh1 = __halves2half2(h2, h3);
    __half2 mm0 = __halves2half2(m0, m1), mm1 = __halves2half2(m2, m3);
    uint2 hp, mp;
    hp.x = *(u32*)&hh0; hp.y = *(u32*)&hh1;
    mp.x = *(u32*)&mm0; mp.y = *(u32*)&mm1;
    *(uint2*)(dh + (size_t)row * D_DIM + q * 4) = hp;
    *(uint2*)(dm + (size_t)row * D_DIM + q * 4) = mp;
}

// ---------------------------------------------------------------------------
// Fused fp16-split HMMA GEMM + argmin. Grid (C/BN=64, M/BM=128), 256 thr,
// 2 CTAs/SM for cross-CTA latency hiding.
__global__ __launch_bounds__(256, 2)
void vq_hmma_kernel(const float* __restrict__ x2g, const float* __restrict__ e2g,
                    ull* __restrict__ best) {
    extern __shared__ __half smh[];
    const u32 sb = smem_u32(smh);
    const int tid = threadIdx.x;
    const int lane = tid & 31;
    const int wid = tid >> 5;
    const int warp_m = wid & 1;       // 0..1 -> 64-row halves
    const int warp_n = wid >> 1;      // 0..3 -> 32-col slices

    const int mrow0 = blockIdx.y * BM;
    const int crow0 = blockIdx.x * BN;

    float* e2s = (float*)((char*)smh + 2 * STAGE_BYTES);
    if (tid < BN) e2s[tid] = e2g[crow0 + tid];

    // ---- cp.async stage loader: 2048 16B tasks, 8 per thread ----
    auto issue = [&](int kb) {
        u32 sbase = sb + (u32)(kb & 1) * STAGE_BYTES;
        int kcol = kb * BK;
#pragma unroll
        for (int i = 0; i < 8; i++) {
            int t = tid + i * 256;
            if (t < 1024) {
                int split = t >> 9, r = (t >> 2) & 127, c = t & 3;
                const __half* g = (split ? g_Am : g_Ah) +
                                  (size_t)(mrow0 + r) * D_DIM + kcol + c * 8;
                u32 s = sbase + (u32)((split ? OFF_AM : OFF_AH) + r * STRIDE + c * 8) * 2;
                cp16(s, g);
            } else {
                int t2 = t - 1024;
                int split = t2 >> 9, r = (t2 >> 2) & 127, c = t2 & 3;
                const __half* g = (split ? g_Bm : g_Bh) +
                                  (size_t)(crow0 + r) * D_DIM + kcol + c * 8;
                u32 s = sbase + (u32)((split ? OFF_BM : OFF_BH) + r * STRIDE + c * 8) * 2;
                cp16(s, g);
            }
        }
        cp_commit();
    };

    float acc[4][4][4];
#pragma unroll
    for (int mt = 0; mt < 4; mt++)
#pragma unroll
        for (int nt = 0; nt < 4; nt++)
#pragma unroll
            for (int r = 0; r < 4; r++) acc[mt][nt][r] = 0.0f;

    issue(0);

    // ---- per-lane ldmatrix base offsets (bytes, relative to stage base) ----
    const int a_r = (lane & 7) + ((lane >> 3) & 1) * 8;
    const int a_k = (lane >> 4) * 8;
    const int b_r = (lane & 7) + (lane >> 4) * 8;
    const int b_k = ((lane >> 3) & 1) * 8;

    u32 aoff[4], boff[2];
#pragma unroll
    for (int mt = 0; mt < 4; mt++)
        aoff[mt] = (u32)((OFF_AH + (warp_m * 64 + mt * 16 + a_r) * STRIDE + a_k) * 2);
#pragma unroll
    for (int p = 0; p < 2; p++)
        boff[p] = (u32)((OFF_BH + (warp_n * 32 + p * 16 + b_r) * STRIDE + b_k) * 2);

    for (int kb = 0; kb < NKB; kb++) {
        if (kb + 1 < NKB) issue(kb + 1);
        if (kb + 1 < NKB) cp_wait<1>(); else cp_wait<0>();
        __syncthreads();

        const u32 sbase = sb + (u32)(kb & 1) * STAGE_BYTES;
#pragma unroll
        for (int ks = 0; ks < 2; ks++) {
            const u32 kbyte = (u32)(ks * 32);   // 16 halfs
            u32 af[4][4], bhf[2][4], bmf[2][4];
#pragma unroll
            for (int mt = 0; mt < 4; mt++) ldsm_x4(af[mt], sbase + aoff[mt] + kbyte);
#pragma unroll
            for (int p = 0; p < 2; p++) ldsm_x4(bhf[p], sbase + boff[p] + kbyte);
#pragma unroll
            for (int p = 0; p < 2; p++) ldsm_x4(bmf[p], sbase + boff[p] + BM_DELTA + kbyte);

#pragma unroll
            for (int mt = 0; mt < 4; mt++)
#pragma unroll
                for (int nt = 0; nt < 4; nt++) {
                    const u32* bf = bhf[nt >> 1];
                    int o = (nt & 1) * 2;
                    mma16816(acc[mt][nt], af[mt][0], af[mt][1], af[mt][2], af[mt][3],
                             bf[o], bf[o + 1]);
                }
#pragma unroll
            for (int mt = 0; mt < 4; mt++)
#pragma unroll
                for (int nt = 0; nt < 4; nt++) {
                    const u32* bf = bmf[nt >> 1];
                    int o = (nt & 1) * 2;
                    mma16816(acc[mt][nt], af[mt][0], af[mt][1], af[mt][2], af[mt][3],
                             bf[o], bf[o + 1]);
                }
            // reuse af regs for Am
#pragma unroll
            for (int mt = 0; mt < 4; mt++) ldsm_x4(af[mt], sbase + aoff[mt] + AM_DELTA + kbyte);
#pragma unroll
            for (int mt = 0; mt < 4; mt++)
#pragma unroll
                for (int nt = 0; nt < 4; nt++) {
                    const u32* bf = bhf[nt >> 1];
                    int o = (nt & 1) * 2;
                    mma16816(acc[mt][nt], af[mt][0], af[mt][1], af[mt][2], af[mt][3],
                             bf[o], bf[o + 1]);
                }
        }
        __syncthreads();
    }

    // ---- epilogue: d2 + argmin ----
    const float inv = 3.0517578125e-05f;   // 2^-15 (exact)
#pragma unroll
    for (int mt = 0; mt < 4; mt++) {
#pragma unroll
        for (int rh = 0; rh < 2; rh++) {
            int m = mrow0 + warp_m * 64 + mt * 16 + (lane >> 2) + rh * 8;
            float x2v = x2g[m];
            ull kbest = 0xFFFFFFFFFFFFFFFFull;
#pragma unroll
            for (int nt = 0; nt < 4; nt++) {
#pragma unroll
                for (int cc = 0; cc < 2; cc++) {
                    int cl = warp_n * 32 + nt * 8 + (lane & 3) * 2 + cc;
                    float xe2 = acc[mt][nt][rh * 2 + cc] * inv;  // = 2*xe, exact scale
                    float t = __fadd_rn(x2v, -xe2);
                    float d2 = __fadd_rn(t, e2s[cl]);
                    ull key = ((ull)__float_as_uint(d2) << 32) | (u32)(crow0 + cl);
                    kbest = (key < kbest) ? key : kbest;
                }
            }
            ull o1 = __shfl_xor_sync(0xFFFFFFFFu, kbest, 1);
            kbest = (o1 < kbest) ? o1 : kbest;
            ull o2 = __shfl_xor_sync(0xFFFFFFFFu, kbest, 2);
            kbest = (o2 < kbest) ? o2 : kbest;
            if ((lane & 3) == 0) atomicMin(&best[m], kbest);
        }
    }
}

// ---------------------------------------------------------------------------
__global__ void finalize_kernel(const float* __restrict__ E,
                                const ull* __restrict__ best,
                                float* __restrict__ out_q,
                                float* __restrict__ out_ind, int write_ind) {
    int row = blockIdx.x * (blockDim.x >> 5) + (threadIdx.x >> 5);
    int lane = threadIdx.x & 31;
    if (row >= M_PTS) return;
    u32 idx = (u32)(best[row] & 0xFFFFFFFFu);
    const float4* src = (const float4*)(E + (size_t)idx * D_DIM);
    float4* dst = (float4*)(out_q + (size_t)row * D_DIM);
    dst[lane]      = src[lane];
    dst[lane + 32] = src[lane + 32];
    if (write_ind && lane == 0) out_ind[row] = (float)idx;
}

// ---------------------------------------------------------------------------
extern "C" void kernel_launch(void* const* d_in, const int* in_sizes, int n_in,
                              void* d_out, int out_size) {
    const float* X = (const float*)d_in[0];
    const float* E = (const float*)d_in[1];
    if (n_in >= 2 && in_sizes[0] == C_CODES * D_DIM && in_sizes[1] == M_PTS * D_DIM) {
        X = (const float*)d_in[1];
        E = (const float*)d_in[0];
    }

    float* out_q = (float*)d_out;
    int write_ind = (out_size >= M_PTS * D_DIM + M_PTS) ? 1 : 0;
    float* out_ind = out_q + (size_t)M_PTS * D_DIM;

    ull* best; float *x2p, *e2p; __half *ah, *am, *bh, *bm;
    cudaGetSymbolAddress((void**)&best, g_best);
    cudaGetSymbolAddress((void**)&x2p, g_x2);
    cudaGetSymbolAddress((void**)&e2p, g_e2);
    cudaGetSymbolAddress((void**)&ah, g_Ah);
    cudaGetSymbolAddress((void**)&am, g_Am);
    cudaGetSymbolAddress((void**)&bh, g_Bh);
    cudaGetSymbolAddress((void**)&bm, g_Bm);

    init_best_kernel<<<(M_PTS + 255) / 256, 256>>>(best, M_PTS);
    rowsumsq_kernel<<<(M_PTS + 7) / 8, 256>>>(X, x2p, M_PTS);
    rowsumsq_kernel<<<(C_CODES + 7) / 8, 256>>>(E, e2p, C_CODES);

    split_kernel<<<(M_PTS * 64 + 255) / 256, 256>>>(X, ah, am, M_PTS, 1.0f);
    split_kernel<<<(C_CODES * 64 + 255) / 256, 256>>>(E, bh, bm, C_CODES, 65536.0f);

    cudaFuncSetAttribute(vq_hmma_kernel, cudaFuncAttributeMaxDynamicSharedMemorySize,
                         SMEM_TOTAL);
    dim3 grid(C_CODES / BN, M_PTS / BM);
    vq_hmma_kernel<<<grid, 256, SMEM_TOTAL>>>(x2p, e2p, best);

    finalize_kernel<<<(M_PTS + 7) / 8, 256>>>(E, best, out_q, out_ind, write_ind);
}